// round 7
// baseline (speedup 1.0000x reference)
#include <cuda_runtime.h>
#include <cuda_fp16.h>
#include <math.h>

#define BB 32
#define HH 1024
#define WW 1024
#define RAD 15            // kernel 31, radius 15
#define INV_K2 (1.0f/961.0f)
#define SMOOTH 0.001f

#define VSEG 64                        // rows per k_vpass block
#define ROWS_PER_HBLK 16               // rows per k_hloss block
#define HBLOCKS (BB * HH / ROWS_PER_HBLK)   // 2048

// Scratch: vertical box-sums of target in fp16 (64 MB), per-batch accumulators.
__device__ __half g_vsum[(size_t)BB * HH * WW];
__device__ float  g_inter[BB];
__device__ float  g_mask[BB];
__device__ int    g_done = 0;

// ---------------------------------------------------------------------------
// Kernel 1: vertical 31-tap box SUM of target (zero padding), fp16 output.
// No shared memory. Thread owns 4 columns (float4); running sums in regs;
// the outgoing row is re-loaded from global (L2 hit; __ldcs = evict-first
// since it is dead after the subtract). First iteration peeled.
// ---------------------------------------------------------------------------
__global__ __launch_bounds__(256) void k_vpass(const float* __restrict__ target) {
    const int b  = blockIdx.y;
    const int y0 = blockIdx.x * VSEG;
    const int x4 = threadIdx.x;                     // float4 / uint2 column index

    if (blockIdx.x == 0 && b == 0 && threadIdx.x < BB) {
        g_inter[threadIdx.x] = 0.0f;
        g_mask[threadIdx.x]  = 0.0f;
    }

    const float4* __restrict__ t4 =
        (const float4*)(target + (size_t)b * HH * WW);
    uint2* __restrict__ vrow =
        (uint2*)(g_vsum + (size_t)b * HH * WW);

    float s0 = 0.f, s1 = 0.f, s2 = 0.f, s3 = 0.f;

    // Preload rows [y0-15, y0+14]
    #pragma unroll 5
    for (int r = y0 - RAD; r < y0 + RAD; r++) {
        if (r >= 0 && r < HH) {
            float4 v = t4[(size_t)r * (WW/4) + x4];
            s0 += v.x; s1 += v.y; s2 += v.z; s3 += v.w;
        }
    }

    // ---- peeled first iteration (y = y0): add incoming row only
    {
        const int ra = y0 + RAD;                    // always < HH (y0 <= 960)
        float4 v = t4[(size_t)ra * (WW/4) + x4];
        s0 += v.x; s1 += v.y; s2 += v.z; s3 += v.w;
        __half2 h01 = __floats2half2_rn(s0, s1);
        __half2 h23 = __floats2half2_rn(s2, s3);
        uint2 pk;
        pk.x = *(const unsigned int*)&h01;
        pk.y = *(const unsigned int*)&h23;
        vrow[(size_t)y0 * (WW/4) + x4] = pk;
    }

    #pragma unroll 4
    for (int y = y0 + 1; y < y0 + VSEG; y++) {
        const int ra = y + RAD;
        if (ra < HH) {
            float4 v = t4[(size_t)ra * (WW/4) + x4];
            s0 += v.x; s1 += v.y; s2 += v.z; s3 += v.w;
        }
        const int rs = y - RAD - 1;
        if (rs >= 0) {                               // dead after this: stream it
            float4 v = __ldcs(&t4[(size_t)rs * (WW/4) + x4]);
            s0 -= v.x; s1 -= v.y; s2 -= v.z; s3 -= v.w;
        }
        __half2 h01 = __floats2half2_rn(s0, s1);
        __half2 h23 = __floats2half2_rn(s2, s3);
        uint2 pk;
        pk.x = *(const unsigned int*)&h01;
        pk.y = *(const unsigned int*)&h23;
        vrow[(size_t)y * (WW/4) + x4] = pk;          // 8B/thread, coalesced
    }
}

// ---------------------------------------------------------------------------
// Kernel 2 (fused): horizontal 31-tap sum over g_vsum + sigmoid + weight +
// per-batch Dice reduction + final scalar (last block via done-counter).
// Window values v[8..31] are folded into the running sum at conversion time;
// only the 7 outgoing (v[1..7]) and 7 incoming (v[32..38]) edge values stay
// live. ALL five window chunks are bounds-checked: for t=0 chunk k=1 is
// below col 0, for t=127 chunk k=3 is past col 1023 (R6 BUG: unchecked ->
// negative-index OOB crash).
// ---------------------------------------------------------------------------
__global__ __launch_bounds__(256, 5) void k_hloss(const float* __restrict__ output,
                                                  const float* __restrict__ target,
                                                  float* __restrict__ lossOut) {
    const int tid  = threadIdx.x;
    const int t    = tid & 127;          // column group: cols [8t, 8t+7]
    const int rsub = tid >> 7;           // 0/1: which of the 2 rows per iter
    const int rowBase = blockIdx.x * ROWS_PER_HBLK;     // global row index
    const int b  = rowBase >> 10;                       // batch (no crossing)
    const int y0 = rowBase & (HH - 1);

    const __half* __restrict__ vs = g_vsum + (size_t)b * HH * WW;
    const float*  __restrict__ tg = target + (size_t)b * HH * WW;
    const float*  __restrict__ op = output + (size_t)b * HH * WW;

    const int c0 = 8 * t - 16;           // window base (col of v[0])
    float li = 0.0f, lm = 0.0f;

    #pragma unroll
    for (int it = 0; it < ROWS_PER_HBLK / 2; it++) {
        const int y = y0 + it * 2 + rsub;

        const uint4* __restrict__ vrow = (const uint4*)(vs + (size_t)y * WW);

        // ---- streamed 40-value fp16 window: fold middles into s, keep edges
        float s = 0.0f;
        float vlo1, vlo2, vlo3, vlo4, vlo5, vlo6, vlo7;       // v[1..7]
        float vhi0, vhi1, vhi2, vhi3, vhi4, vhi5, vhi6;       // v[32..38]

        // k = 0: v[0..7] -> keep v[1..7], add them to s (v[0] unused)
        {
            const int cb = c0;
            float f1,f2,f3,f4,f5,f6,f7;
            if (cb >= 0) {                           // cb <= 1000 always
                uint4 u = vrow[cb >> 3];
                float2 a = __half22float2(*(const __half2*)&u.x);
                float2 bq = __half22float2(*(const __half2*)&u.y);
                float2 c = __half22float2(*(const __half2*)&u.z);
                float2 d = __half22float2(*(const __half2*)&u.w);
                f1=a.y; f2=bq.x; f3=bq.y; f4=c.x; f5=c.y; f6=d.x; f7=d.y;
            } else {
                f1=f2=f3=f4=f5=f6=f7=0.f;
            }
            vlo1=f1; vlo2=f2; vlo3=f3; vlo4=f4; vlo5=f5; vlo6=f6; vlo7=f7;
            s += f1+f2+f3+f4+f5+f6+f7;
        }
        // k = 1..3: v[8..31] -> fold into s only.
        // NOT always in bounds: t=0 -> k=1 chunk at col -8; t=127 -> k=3
        // chunk at col 1024. Predicate each chunk (zero contribution OOB).
        #pragma unroll
        for (int k = 1; k <= 3; k++) {
            const int cb = c0 + 8*k;
            if (cb >= 0 && cb < WW) {
                uint4 u = vrow[cb >> 3];
                float2 a = __half22float2(*(const __half2*)&u.x);
                float2 bq = __half22float2(*(const __half2*)&u.y);
                float2 c = __half22float2(*(const __half2*)&u.z);
                float2 d = __half22float2(*(const __half2*)&u.w);
                s += a.x+a.y+bq.x+bq.y+c.x+c.y+d.x+d.y;
            }
        }
        // k = 4: v[32..39] -> keep v[32..38] (v[39] unused)
        {
            const int cb = c0 + 32;
            if (cb < WW) {                           // cb >= 16 always
                uint4 u = vrow[cb >> 3];
                float2 a = __half22float2(*(const __half2*)&u.x);
                float2 bq = __half22float2(*(const __half2*)&u.y);
                float2 c = __half22float2(*(const __half2*)&u.z);
                float2 d = __half22float2(*(const __half2*)&u.w);
                vhi0=a.x; vhi1=a.y; vhi2=bq.x; vhi3=bq.y;
                vhi4=c.x; vhi5=c.y; vhi6=d.x;
            } else {
                vhi0=vhi1=vhi2=vhi3=vhi4=vhi5=vhi6=0.f;
            }
        }

        // ---- target / output: 2 float4 each, single-use -> streaming loads
        const float4* __restrict__ trow = (const float4*)(tg + (size_t)y * WW);
        const float4* __restrict__ orow = (const float4*)(op + (size_t)y * WW);
        float4 ta = __ldcs(&trow[2*t]), tb = __ldcs(&trow[2*t+1]);
        float4 oa = __ldcs(&orow[2*t]), ob = __ldcs(&orow[2*t+1]);
        float tv[8] = {ta.x, ta.y, ta.z, ta.w, tb.x, tb.y, tb.z, tb.w};
        float ov[8] = {oa.x, oa.y, oa.z, oa.w, ob.x, ob.y, ob.z, ob.w};

        float inc[7] = {vhi0, vhi1, vhi2, vhi3, vhi4, vhi5, vhi6};
        float out7[7] = {vlo1, vlo2, vlo3, vlo4, vlo5, vlo6, vlo7};

        #pragma unroll
        for (int k = 0; k < 8; k++) {
            if (k) s += inc[k-1] - out7[k-1];        // slide window
            const float avg = s * INV_K2;
            const float w   = 1.0f + 5.0f * fabsf(avg - tv[k]);
            const float sig = 1.0f / (1.0f + __expf(-ov[k]));
            li += sig * tv[k] * w;
            lm += (tv[k] + sig) * w;
        }
    }

    // ---- block reduction (8 warps) + per-batch atomics
    __shared__ float red_i[8], red_m[8];
    __shared__ bool  isLast;
    #pragma unroll
    for (int off = 16; off > 0; off >>= 1) {
        li += __shfl_down_sync(0xFFFFFFFFu, li, off);
        lm += __shfl_down_sync(0xFFFFFFFFu, lm, off);
    }
    const int warp = tid >> 5, lane = tid & 31;
    if (lane == 0) { red_i[warp] = li; red_m[warp] = lm; }
    __syncthreads();
    if (tid == 0) {
        float si = 0.f, sm = 0.f;
        #pragma unroll
        for (int w = 0; w < 8; w++) { si += red_i[w]; sm += red_m[w]; }
        atomicAdd(&g_inter[b], si);
        atomicAdd(&g_mask[b], sm);
        __threadfence();
        int c = atomicAdd(&g_done, 1);
        isLast = (c == HBLOCKS - 1);
    }
    __syncthreads();

    if (isLast && tid == 0) {
        __threadfence();
        float l = 0.0f;
        #pragma unroll
        for (int k = 0; k < BB; k++)
            l += 1.0f - (2.0f * g_inter[k] + SMOOTH) / (g_mask[k] + SMOOTH);
        lossOut[0] = l * (1.0f / (float)BB);
        g_done = 0;                                  // reset for graph replay
    }
}

// ---------------------------------------------------------------------------
extern "C" void kernel_launch(void* const* d_in, const int* in_sizes, int n_in,
                              void* d_out, int out_size) {
    const float* output = (const float*)d_in[0];   // metadata order: output, target
    const float* target = (const float*)d_in[1];
    float* out = (float*)d_out;

    dim3 vgrid(HH / VSEG, BB);                     // (16, 32)
    k_vpass<<<vgrid, 256>>>(target);
    k_hloss<<<HBLOCKS, 256>>>(output, target, out);
}